// round 1
// baseline (speedup 1.0000x reference)
#include <cuda_runtime.h>
#include <cuda_bf16.h>

// Recall_53077205844588: masked mean of remapped `predicted` over gt!=0.
// predicted: [B=32, F=512, T=2048] fp32; gt: same shape int32 in {0,1}.
// result = sum_{gt!=0} predicted[b, f==0?1:f, t==0?1:t] / count, or 0 if count==0.

#define B_DIM 32
#define F_DIM 512
#define T_DIM 2048
#define N_ELEMS (B_DIM * F_DIM * T_DIM)      // 33,554,432
#define N_VEC   (N_ELEMS / 4)                // 8,388,608 float4 groups
#define NBLOCKS 2048
#define NTHREADS 256

__device__ float        g_partial_sum[NBLOCKS];
__device__ unsigned int g_partial_cnt[NBLOCKS];

__global__ __launch_bounds__(NTHREADS) void recall_partial_kernel(
    const float* __restrict__ pred,
    const int*   __restrict__ gt)
{
    float        local_sum = 0.0f;
    unsigned int local_cnt = 0;

    const int stride = gridDim.x * blockDim.x;
    for (int v = blockIdx.x * blockDim.x + threadIdx.x; v < N_VEC; v += stride) {
        const int i = v * 4;                  // element index of lane .x
        const int t_base = i & (T_DIM - 1);   // t of lane .x (T_DIM power of 2)
        const int row    = i >> 11;           // i / T_DIM  (b*F + f)
        const int f      = row & (F_DIM - 1); // row % F_DIM

        // Row remap: f==0 reads row f=1 (offset +T_DIM floats, keeps 16B align)
        const int p_off = (f == 0) ? T_DIM : 0;

        float4 p = __ldg((const float4*)(pred + i + p_off));
        int4   g = __ldg((const int4*)(gt + i));

        // Column remap: t==0 -> t'=1 is exactly lane .y of this same vector.
        if (t_base == 0) p.x = p.y;

        if (g.x) { local_sum += p.x; local_cnt++; }
        if (g.y) { local_sum += p.y; local_cnt++; }
        if (g.z) { local_sum += p.z; local_cnt++; }
        if (g.w) { local_sum += p.w; local_cnt++; }
    }

    // Warp reduction
    #pragma unroll
    for (int off = 16; off > 0; off >>= 1) {
        local_sum += __shfl_down_sync(0xffffffffu, local_sum, off);
        local_cnt += __shfl_down_sync(0xffffffffu, local_cnt, off);
    }

    __shared__ float        s_sum[NTHREADS / 32];
    __shared__ unsigned int s_cnt[NTHREADS / 32];
    const int lane = threadIdx.x & 31;
    const int wid  = threadIdx.x >> 5;
    if (lane == 0) { s_sum[wid] = local_sum; s_cnt[wid] = local_cnt; }
    __syncthreads();

    if (wid == 0) {
        float        bs = (lane < NTHREADS / 32) ? s_sum[lane] : 0.0f;
        unsigned int bc = (lane < NTHREADS / 32) ? s_cnt[lane] : 0u;
        #pragma unroll
        for (int off = 4; off > 0; off >>= 1) {
            bs += __shfl_down_sync(0xffffffffu, bs, off);
            bc += __shfl_down_sync(0xffffffffu, bc, off);
        }
        if (lane == 0) {
            g_partial_sum[blockIdx.x] = bs;
            g_partial_cnt[blockIdx.x] = bc;
        }
    }
}

__global__ __launch_bounds__(1024) void recall_finalize_kernel(float* __restrict__ out)
{
    // One block reduces NBLOCKS partials.
    float        local_sum = 0.0f;
    unsigned int local_cnt = 0;
    for (int i = threadIdx.x; i < NBLOCKS; i += blockDim.x) {
        local_sum += g_partial_sum[i];
        local_cnt += g_partial_cnt[i];
    }

    #pragma unroll
    for (int off = 16; off > 0; off >>= 1) {
        local_sum += __shfl_down_sync(0xffffffffu, local_sum, off);
        local_cnt += __shfl_down_sync(0xffffffffu, local_cnt, off);
    }

    __shared__ float        s_sum[32];
    __shared__ unsigned int s_cnt[32];
    const int lane = threadIdx.x & 31;
    const int wid  = threadIdx.x >> 5;
    if (lane == 0) { s_sum[wid] = local_sum; s_cnt[wid] = local_cnt; }
    __syncthreads();

    if (wid == 0) {
        const int nwarps = blockDim.x >> 5;
        float        bs = (lane < nwarps) ? s_sum[lane] : 0.0f;
        unsigned int bc = (lane < nwarps) ? s_cnt[lane] : 0u;
        #pragma unroll
        for (int off = 16; off > 0; off >>= 1) {
            bs += __shfl_down_sync(0xffffffffu, bs, off);
            bc += __shfl_down_sync(0xffffffffu, bc, off);
        }
        if (lane == 0) {
            out[0] = (bc > 0u) ? (bs / (float)bc) : 0.0f;
        }
    }
}

extern "C" void kernel_launch(void* const* d_in, const int* in_sizes, int n_in,
                              void* d_out, int out_size)
{
    const float* pred = (const float*)d_in[0];
    const int*   gt   = (const int*)d_in[1];
    float*       out  = (float*)d_out;

    recall_partial_kernel<<<NBLOCKS, NTHREADS>>>(pred, gt);
    recall_finalize_kernel<<<1, 1024>>>(out);
}

// round 2
// speedup vs baseline: 1.0877x; 1.0877x over previous
#include <cuda_runtime.h>
#include <cuda_bf16.h>

// Recall_53077205844588: masked mean of remapped `predicted` over gt!=0.
// predicted: [B=32, F=512, T=2048] fp32; gt: same shape int32 in {0,1}.
// result = sum_{gt!=0} predicted[b, f==0?1:f, t==0?1:t] / count, or 0 if count==0.
// Single fused kernel: grid-stride partials + last-block-done final reduce.

#define B_DIM 32
#define F_DIM 512
#define T_DIM 2048
#define N_ELEMS (B_DIM * F_DIM * T_DIM)       // 33,554,432
#define N_VEC   (N_ELEMS / 4)                 // 8,388,608 float4 groups
#define NBLOCKS 2048
#define NTHREADS 256
#define TOTAL_THREADS (NBLOCKS * NTHREADS)    // 524,288
#define ITERS (N_VEC / TOTAL_THREADS)         // 16 exact

__device__ float        g_partial_sum[NBLOCKS];
__device__ unsigned int g_partial_cnt[NBLOCKS];
__device__ unsigned int g_done_counter = 0;   // atomicInc wraps back to 0 -> graph-replay safe

__device__ __forceinline__ void block_reduce_write(float v, unsigned int c,
                                                   float* out_s, unsigned int* out_c)
{
    #pragma unroll
    for (int off = 16; off > 0; off >>= 1) {
        v += __shfl_down_sync(0xffffffffu, v, off);
        c += __shfl_down_sync(0xffffffffu, c, off);
    }
    __shared__ float        s_sum[NTHREADS / 32];
    __shared__ unsigned int s_cnt[NTHREADS / 32];
    const int lane = threadIdx.x & 31;
    const int wid  = threadIdx.x >> 5;
    if (lane == 0) { s_sum[wid] = v; s_cnt[wid] = c; }
    __syncthreads();
    if (wid == 0) {
        float        bs = (lane < NTHREADS / 32) ? s_sum[lane] : 0.0f;
        unsigned int bc = (lane < NTHREADS / 32) ? s_cnt[lane] : 0u;
        #pragma unroll
        for (int off = 4; off > 0; off >>= 1) {
            bs += __shfl_down_sync(0xffffffffu, bs, off);
            bc += __shfl_down_sync(0xffffffffu, bc, off);
        }
        if (lane == 0) { *out_s = bs; *out_c = bc; }
    }
    __syncthreads();   // re-usable shared for final phase
}

__global__ __launch_bounds__(NTHREADS) void recall_fused_kernel(
    const float* __restrict__ pred,
    const int*   __restrict__ gt,
    float*       __restrict__ out)
{
    float        local_sum = 0.0f;
    unsigned int local_cnt = 0;

    const int base = blockIdx.x * NTHREADS + threadIdx.x;

    #pragma unroll 4
    for (int it = 0; it < ITERS; it++) {
        const int v = it * TOTAL_THREADS + base;
        const int i = v * 4;                   // element index of lane .x
        const int t_base = i & (T_DIM - 1);    // t of lane .x
        const int row    = i >> 11;            // i / T_DIM  (b*F + f)
        const int f      = row & (F_DIM - 1);  // row % F_DIM

        // Row remap: f==0 reads row f=1 (offset +T_DIM floats, keeps 16B align)
        const int p_off = (f == 0) ? T_DIM : 0;

        float4 p = __ldg((const float4*)(pred + i + p_off));
        int4   g = __ldg((const int4*)(gt + i));

        // Column remap: t==0 -> t'=1 is lane .y of this same vector.
        if (t_base == 0) p.x = p.y;

        if (g.x) { local_sum += p.x; local_cnt++; }
        if (g.y) { local_sum += p.y; local_cnt++; }
        if (g.z) { local_sum += p.z; local_cnt++; }
        if (g.w) { local_sum += p.w; local_cnt++; }
    }

    float        blk_sum;
    unsigned int blk_cnt;
    block_reduce_write(local_sum, local_cnt, &blk_sum, &blk_cnt);

    __shared__ bool s_is_last;
    if (threadIdx.x == 0) {
        g_partial_sum[blockIdx.x] = blk_sum;
        g_partial_cnt[blockIdx.x] = blk_cnt;
        __threadfence();
        unsigned int prev = atomicInc(&g_done_counter, NBLOCKS - 1); // wraps to 0 at NBLOCKS
        s_is_last = (prev == NBLOCKS - 1);
    }
    __syncthreads();

    if (s_is_last) {
        // Last block: reduce all NBLOCKS partials (2048 / 256 = 8 each).
        float        fs = 0.0f;
        unsigned int fc = 0;
        #pragma unroll
        for (int j = 0; j < NBLOCKS / NTHREADS; j++) {
            const int idx = j * NTHREADS + threadIdx.x;
            fs += g_partial_sum[idx];
            fc += g_partial_cnt[idx];
        }
        float        tot_sum;
        unsigned int tot_cnt;
        block_reduce_write(fs, fc, &tot_sum, &tot_cnt);
        if (threadIdx.x == 0) {
            out[0] = (tot_cnt > 0u) ? (tot_sum / (float)tot_cnt) : 0.0f;
        }
    }
}

extern "C" void kernel_launch(void* const* d_in, const int* in_sizes, int n_in,
                              void* d_out, int out_size)
{
    const float* pred = (const float*)d_in[0];
    const int*   gt   = (const int*)d_in[1];
    float*       out  = (float*)d_out;

    recall_fused_kernel<<<NBLOCKS, NTHREADS>>>(pred, gt, out);
}